// round 5
// baseline (speedup 1.0000x reference)
#include <cuda_runtime.h>
#include <cstdint>
#include <cstddef>

namespace {

constexpr int THREADS   = 448;   // 14 warps
constexpr int BPB       = 16;    // batches per block
constexpr int ROWS      = 224;   // BPB * 14
constexpr int XS_STRIDE = 36;    // 36 % 32 == 4 -> A-frag conflict-free
constexpr int WS_STRIDE = 136;   // 136 % 32 == 8 -> B-frag conflict-free
constexpr int HS_STRIDE = 132;   // 132 % 32 == 4 -> A-frag conflict-free
constexpr int W2S_STRIDE = 72;   // 72 % 32 == 8 -> B-frag conflict-free
constexpr int ZS_STRIDE = 72;

constexpr int XBUF      = ROWS * XS_STRIDE;     // 8064 floats per buffer
constexpr int WBUF      = 32 * WS_STRIDE;       // 4352 floats per buffer
constexpr int WS_OFF    = 2 * XBUF;             // 16128
constexpr int HS_FLOATS = ROWS * HS_STRIDE;     // 29568 (aliases X/W buffers)
constexpr int W2S_OFF   = HS_FLOATS;            // 29568
constexpr int SMEM_FLOATS = W2S_OFF + 128 * W2S_STRIDE;  // 38784
constexpr int SMEM_BYTES  = SMEM_FLOATS * 4;             // 155136

__device__ __forceinline__ float to_tf32(float x) {
    unsigned u;
    asm("cvt.rna.tf32.f32 %0, %1;" : "=r"(u) : "f"(x));
    return __uint_as_float(u);
}

__device__ __forceinline__ void mma8(float* d,
                                     float a0, float a1, float a2, float a3,
                                     float b0, float b1) {
    asm volatile(
        "mma.sync.aligned.m16n8k8.row.col.f32.tf32.tf32.f32 "
        "{%0,%1,%2,%3}, {%4,%5,%6,%7}, {%8,%9}, {%0,%1,%2,%3};\n"
        : "+f"(d[0]), "+f"(d[1]), "+f"(d[2]), "+f"(d[3])
        : "r"(__float_as_uint(a0)), "r"(__float_as_uint(a1)),
          "r"(__float_as_uint(a2)), "r"(__float_as_uint(a3)),
          "r"(__float_as_uint(b0)), "r"(__float_as_uint(b1)));
}

// Hardcoded A_hat = D^{-1/2}(A+I)D^{-1/2} for the fixed 14-tooth graph.
// Degrees (with self-loop): [3,4,4,4,4,4,3, 3,4,4,4,4,4,3].
__device__ __forceinline__ void ahat14(const float* y, float* o) {
    const float A = 0.3333333333333333f;   // 1/sqrt(3*3)
    const float B = 0.28867513459481287f;  // 1/sqrt(3*4)
    const float C = 0.25f;                 // 1/sqrt(4*4)
    o[0]  = A*y[0] + B*y[1] + A*y[7];
    o[1]  = B*y[0] + C*y[1] + C*y[2]  + C*y[8];
    o[2]  = C*y[1] + C*y[2] + C*y[3]  + C*y[9];
    o[3]  = C*y[2] + C*y[3] + C*y[4]  + C*y[10];
    o[4]  = C*y[3] + C*y[4] + C*y[5]  + C*y[11];
    o[5]  = C*y[4] + C*y[5] + B*y[6]  + C*y[12];
    o[6]  = B*y[5] + A*y[6] + A*y[13];
    o[7]  = A*y[0] + A*y[7] + B*y[8];
    o[8]  = C*y[1] + B*y[7] + C*y[8]  + C*y[9];
    o[9]  = C*y[2] + C*y[8] + C*y[9]  + C*y[10];
    o[10] = C*y[3] + C*y[9] + C*y[10] + C*y[11];
    o[11] = C*y[4] + C*y[10]+ C*y[11] + C*y[12];
    o[12] = C*y[5] + C*y[11]+ C*y[12] + B*y[13];
    o[13] = A*y[6] + B*y[12]+ A*y[13];
}

} // namespace

__global__ void __launch_bounds__(THREADS, 1)
gcn_fused_kernel(const float* __restrict__ fea,
                 const float* __restrict__ W1,
                 const float* __restrict__ b1,
                 const float* __restrict__ W2,
                 const float* __restrict__ b2,
                 float* __restrict__ out)
{
    extern __shared__ float sm[];
    float* Xs  = sm;              // [2][ROWS][36]  (GEMM1 X double buffer)
    float* Ws  = sm + WS_OFF;     // [2][32][136]   (GEMM1 W1 double buffer)
    float* Hs  = sm;              // [ROWS][132]    aliases X/W buffers
    float* W2s = sm + W2S_OFF;    // [128][72]
    float* Zs  = sm;              // [ROWS][72]     aliases Hs (after GEMM2)

    const int tid  = threadIdx.x;
    const int warp = tid >> 5;
    const int lane = tid & 31;
    const int g = lane >> 2;   // groupID
    const int t = lane & 3;    // threadID_in_group
    const int wm = warp >> 1;  // 0..6  (M tile, 32 rows)
    const int wn = warp & 1;   // 0..1  (N tile)
    const int blk = blockIdx.x;

    // ---------------- stage W2 -> smem (tf32) ----------------
    #pragma unroll
    for (int j = 0; j < 5; ++j) {
        int idx = tid + j * THREADS;
        if (idx < 2048) {                  // 128*64/4 float4s
            int kr = idx >> 4;
            int q  = (idx & 15) << 2;
            float4 v = *reinterpret_cast<const float4*>(W2 + kr * 64 + q);
            *reinterpret_cast<float4*>(W2s + kr * W2S_STRIDE + q) =
                make_float4(to_tf32(v.x), to_tf32(v.y), to_tf32(v.z), to_tf32(v.w));
        }
    }

    const float* feaB = fea + (size_t)blk * ROWS * 256;

    float4 xr[4];   // X prefetch: 1792 float4 / 448 threads = 4 each
    float4 wr[3];   // W prefetch: 1024 float4 -> 2-3 each

    // ---------------- GEMM1 prologue: chunk 0 ----------------
    #pragma unroll
    for (int j = 0; j < 4; ++j) {
        int idx = tid + j * THREADS;
        int r = idx >> 3, q = (idx & 7) << 2;
        xr[j] = *reinterpret_cast<const float4*>(feaB + r * 256 + q);
    }
    #pragma unroll
    for (int j = 0; j < 3; ++j) {
        int idx = tid + j * THREADS;
        if (idx < 1024) {
            int kr = idx >> 5, q = (idx & 31) << 2;
            wr[j] = *reinterpret_cast<const float4*>(W1 + kr * 128 + q);
        }
    }
    #pragma unroll
    for (int j = 0; j < 4; ++j) {
        int idx = tid + j * THREADS;
        int r = idx >> 3, q = (idx & 7) << 2;
        float4 v = xr[j];
        *reinterpret_cast<float4*>(Xs + r * XS_STRIDE + q) =
            make_float4(to_tf32(v.x), to_tf32(v.y), to_tf32(v.z), to_tf32(v.w));
    }
    #pragma unroll
    for (int j = 0; j < 3; ++j) {
        int idx = tid + j * THREADS;
        if (idx < 1024) {
            int kr = idx >> 5, q = (idx & 31) << 2;
            float4 v = wr[j];
            *reinterpret_cast<float4*>(Ws + kr * WS_STRIDE + q) =
                make_float4(to_tf32(v.x), to_tf32(v.y), to_tf32(v.z), to_tf32(v.w));
        }
    }
    __syncthreads();

    // ---------------- GEMM1 main loop: Y = X * W1 ----------------
    float acc[2][8][4];
    #pragma unroll
    for (int mt = 0; mt < 2; ++mt)
        #pragma unroll
        for (int nt = 0; nt < 8; ++nt)
            #pragma unroll
            for (int i = 0; i < 4; ++i) acc[mt][nt][i] = 0.f;

    #pragma unroll 1
    for (int c = 0; c < 8; ++c) {
        // prefetch next chunk into registers (overlaps with mma below)
        if (c < 7) {
            int k0 = (c + 1) * 32;
            #pragma unroll
            for (int j = 0; j < 4; ++j) {
                int idx = tid + j * THREADS;
                int r = idx >> 3, q = (idx & 7) << 2;
                xr[j] = *reinterpret_cast<const float4*>(feaB + r * 256 + k0 + q);
            }
            #pragma unroll
            for (int j = 0; j < 3; ++j) {
                int idx = tid + j * THREADS;
                if (idx < 1024) {
                    int kr = idx >> 5, q = (idx & 31) << 2;
                    wr[j] = *reinterpret_cast<const float4*>(W1 + (k0 + kr) * 128 + q);
                }
            }
        }

        const float* xb = Xs + (c & 1) * XBUF;
        const float* wb = Ws + (c & 1) * WBUF;
        #pragma unroll
        for (int ks = 0; ks < 4; ++ks) {
            float a[2][4];
            #pragma unroll
            for (int mt = 0; mt < 2; ++mt) {
                const float* ap = xb + (wm * 32 + mt * 16 + g) * XS_STRIDE + ks * 8 + t;
                a[mt][0] = ap[0];
                a[mt][1] = ap[8 * XS_STRIDE];
                a[mt][2] = ap[4];
                a[mt][3] = ap[8 * XS_STRIDE + 4];
            }
            #pragma unroll
            for (int nt = 0; nt < 8; ++nt) {
                const float* bp = wb + (ks * 8 + t) * WS_STRIDE + wn * 64 + nt * 8 + g;
                float b0  = bp[0];
                float b1v = bp[4 * WS_STRIDE];
                mma8(acc[0][nt], a[0][0], a[0][1], a[0][2], a[0][3], b0, b1v);
                mma8(acc[1][nt], a[1][0], a[1][1], a[1][2], a[1][3], b0, b1v);
            }
        }

        // store prefetched chunk into the other buffer.
        // Safe: that buffer was last READ in chunk c-1, and the sync that
        // ended iteration c-1 ordered all those reads before these writes.
        if (c < 7) {
            float* xw = Xs + ((c + 1) & 1) * XBUF;
            float* ww = Ws + ((c + 1) & 1) * WBUF;
            #pragma unroll
            for (int j = 0; j < 4; ++j) {
                int idx = tid + j * THREADS;
                int r = idx >> 3, q = (idx & 7) << 2;
                float4 v = xr[j];
                *reinterpret_cast<float4*>(xw + r * XS_STRIDE + q) =
                    make_float4(to_tf32(v.x), to_tf32(v.y), to_tf32(v.z), to_tf32(v.w));
            }
            #pragma unroll
            for (int j = 0; j < 3; ++j) {
                int idx = tid + j * THREADS;
                if (idx < 1024) {
                    int kr = idx >> 5, q = (idx & 31) << 2;
                    float4 v = wr[j];
                    *reinterpret_cast<float4*>(ww + kr * WS_STRIDE + q) =
                        make_float4(to_tf32(v.x), to_tf32(v.y), to_tf32(v.z), to_tf32(v.w));
                }
            }
        }
        __syncthreads();
    }

    // ---------------- write Y (pre-aggregation, f32) -> Hs ----------------
    // Hs aliases the X/W buffers; the loop ended with __syncthreads().
    #pragma unroll
    for (int mt = 0; mt < 2; ++mt) {
        int r0 = wm * 32 + mt * 16 + g;
        #pragma unroll
        for (int nt = 0; nt < 8; ++nt) {
            int col = wn * 64 + nt * 8 + 2 * t;
            *reinterpret_cast<float2*>(Hs + r0 * HS_STRIDE + col) =
                make_float2(acc[mt][nt][0], acc[mt][nt][1]);
            *reinterpret_cast<float2*>(Hs + (r0 + 8) * HS_STRIDE + col) =
                make_float2(acc[mt][nt][2], acc[mt][nt][3]);
        }
    }
    __syncthreads();

    // ---------------- A_hat pass 1 (+b1, relu, cvt tf32), in place ----------------
    for (int task = tid; task < BPB * 128; task += THREADS) {
        int batch = task >> 7;
        int col   = task & 127;
        float* base = Hs + batch * 14 * HS_STRIDE + col;
        float y[14], h[14];
        #pragma unroll
        for (int i = 0; i < 14; ++i) y[i] = base[i * HS_STRIDE];
        ahat14(y, h);
        float bv = b1[col];
        #pragma unroll
        for (int i = 0; i < 14; ++i) {
            float v = fmaxf(h[i] + bv, 0.f);
            base[i * HS_STRIDE] = to_tf32(v);
        }
    }
    __syncthreads();

    // ---------------- GEMM2: Z = H * W2 ----------------
    float acc2[2][4][4];
    #pragma unroll
    for (int mt = 0; mt < 2; ++mt)
        #pragma unroll
        for (int nt = 0; nt < 4; ++nt)
            #pragma unroll
            for (int i = 0; i < 4; ++i) acc2[mt][nt][i] = 0.f;

    #pragma unroll
    for (int ks = 0; ks < 16; ++ks) {
        float a[2][4];
        #pragma unroll
        for (int mt = 0; mt < 2; ++mt) {
            const float* ap = Hs + (wm * 32 + mt * 16 + g) * HS_STRIDE + ks * 8 + t;
            a[mt][0] = ap[0];
            a[mt][1] = ap[8 * HS_STRIDE];
            a[mt][2] = ap[4];
            a[mt][3] = ap[8 * HS_STRIDE + 4];
        }
        #pragma unroll
        for (int nt = 0; nt < 4; ++nt) {
            const float* bp = W2s + (ks * 8 + t) * W2S_STRIDE + wn * 32 + nt * 8 + g;
            float b0  = bp[0];
            float b1v = bp[4 * W2S_STRIDE];
            mma8(acc2[0][nt], a[0][0], a[0][1], a[0][2], a[0][3], b0, b1v);
            mma8(acc2[1][nt], a[1][0], a[1][1], a[1][2], a[1][3], b0, b1v);
        }
    }
    __syncthreads();   // all Hs reads complete before Zs writes (alias)

    // ---------------- write Z -> Zs ----------------
    #pragma unroll
    for (int mt = 0; mt < 2; ++mt) {
        int r0 = wm * 32 + mt * 16 + g;
        #pragma unroll
        for (int nt = 0; nt < 4; ++nt) {
            int col = wn * 32 + nt * 8 + 2 * t;
            *reinterpret_cast<float2*>(Zs + r0 * ZS_STRIDE + col) =
                make_float2(acc2[mt][nt][0], acc2[mt][nt][1]);
            *reinterpret_cast<float2*>(Zs + (r0 + 8) * ZS_STRIDE + col) =
                make_float2(acc2[mt][nt][2], acc2[mt][nt][3]);
        }
    }
    __syncthreads();

    // ---------------- A_hat pass 2 (+b2) -> global ----------------
    float* gout = out + (size_t)blk * ROWS * 64;
    for (int task = tid; task < BPB * 64; task += THREADS) {
        int batch = task >> 6;
        int col   = task & 63;
        const float* base = Zs + batch * 14 * ZS_STRIDE + col;
        float z[14], o[14];
        #pragma unroll
        for (int i = 0; i < 14; ++i) z[i] = base[i * ZS_STRIDE];
        ahat14(z, o);
        float bv = b2[col];
        #pragma unroll
        for (int m = 0; m < 14; ++m)
            gout[(batch * 14 + m) * 64 + col] = o[m] + bv;
    }
}

extern "C" void kernel_launch(void* const* d_in, const int* in_sizes, int n_in,
                              void* d_out, int out_size) {
    const float* fea = (const float*)d_in[0];
    const float* W1  = (const float*)d_in[1];
    const float* b1  = (const float*)d_in[2];
    const float* W2  = (const float*)d_in[3];
    const float* b2  = (const float*)d_in[4];
    float* out = (float*)d_out;

    int B = in_sizes[0] / (14 * 256);   // 16384
    int blocks = B / BPB;               // 1024

    cudaFuncSetAttribute(gcn_fused_kernel,
                         cudaFuncAttributeMaxDynamicSharedMemorySize, SMEM_BYTES);
    gcn_fused_kernel<<<blocks, THREADS, SMEM_BYTES>>>(fea, W1, b1, W2, b2, out);
}

// round 7
// speedup vs baseline: 1.1300x; 1.1300x over previous
#include <cuda_runtime.h>
#include <cuda_fp16.h>
#include <cstdint>
#include <cstddef>

// pre-converted fp16 weights, transposed to [n][k]
__device__ __align__(16) __half g_W1h[128 * 256];
__device__ __align__(16) __half g_W2h[64 * 128];

namespace {

constexpr int THREADS = 448;   // 14 warps
constexpr int BPB     = 8;
constexpr int ROWS    = 112;   // 8 * 14

// word (4B) strides, all ≡ 4 (mod 8) where fragment-LDS needs it
constexpr int XSW  = 20;   // X fp16 chunk: [112][16+4 pad] words
constexpr int WSW  = 20;   // W1 fp16 chunk: [128][16+4] words
constexpr int HSW  = 68;   // H fp16: [112][64+4] words
constexpr int W2SW = 68;   // W2T fp16: [64][64+4] words
constexpr int YSF  = 136;  // Y f32 stride (floats)
constexpr int ZSF  = 72;   // Z f32 stride

constexpr int XBUFW = ROWS * XSW;   // 2240 words per buffer
constexpr int WBUFW = 128 * WSW;    // 2560 words per buffer

// byte offsets
constexpr int O_BIAS = 0;                      // b1 (512B) + b2 (256B)
constexpr int O_Y    = 1024;                   // Y f32: 112*136*4 = 60928
constexpr int O_X    = 1024;                   // alias: X dbl buf 17920
constexpr int O_W1   = O_X + 2 * XBUFW * 4;    // 18944: W1 dbl buf 20480
constexpr int O_Z    = 1024;                   // alias: Z f32 32256
constexpr int O_H    = O_Y + ROWS * YSF * 4;   // 61952: H 30464
constexpr int O_W2   = O_H + ROWS * HSW * 4;   // 92416: W2 17408
constexpr int SMEM_BYTES = O_W2 + 64 * W2SW * 4;  // 109824

__device__ __forceinline__ uint32_t packh2(float a, float b) {
    __half2 h = __floats2half2_rn(a, b);
    return *reinterpret_cast<uint32_t*>(&h);
}

__device__ __forceinline__ void mma16816(float* d,
                                         uint32_t a0, uint32_t a1, uint32_t a2, uint32_t a3,
                                         uint32_t b0, uint32_t b1) {
    asm volatile(
        "mma.sync.aligned.m16n8k16.row.col.f32.f16.f16.f32 "
        "{%0,%1,%2,%3},{%4,%5,%6,%7},{%8,%9},{%0,%1,%2,%3};\n"
        : "+f"(d[0]), "+f"(d[1]), "+f"(d[2]), "+f"(d[3])
        : "r"(a0), "r"(a1), "r"(a2), "r"(a3), "r"(b0), "r"(b1));
}

__device__ __forceinline__ void cp16(uint32_t dst_smem, const void* src) {
    asm volatile("cp.async.ca.shared.global [%0], [%1], 16;\n"
                 :: "r"(dst_smem), "l"(src));
}
__device__ __forceinline__ void cp_commit() {
    asm volatile("cp.async.commit_group;\n" ::: "memory");
}
__device__ __forceinline__ void cp_wait0() {
    asm volatile("cp.async.wait_group 0;\n" ::: "memory");
}

// A_hat coefficients: degrees (with self-loop) = 3 at teeth {0,6,7,13}, else 4
constexpr float CA = 0.3333333333333333f;   // 1/sqrt(3*3)
constexpr float CB = 0.28867513459481287f;  // 1/sqrt(3*4)
constexpr float CC = 0.25f;                 // 1/sqrt(4*4)

__device__ __forceinline__ float2 m3(float wa, float2 a, float wb, float2 b,
                                     float wc, float2 c) {
    return make_float2(wa * a.x + wb * b.x + wc * c.x,
                       wa * a.y + wb * b.y + wc * c.y);
}
__device__ __forceinline__ float2 m4(float wa, float2 a, float wb, float2 b,
                                     float wc, float2 c, float wd, float2 d) {
    return make_float2(wa * a.x + wb * b.x + wc * c.x + wd * d.x,
                       wa * a.y + wb * b.y + wc * c.y + wd * d.y);
}

__device__ __forceinline__ void ahat14(const float* y, float* o) {
    o[0]  = CA*y[0] + CB*y[1] + CA*y[7];
    o[1]  = CB*y[0] + CC*y[1] + CC*y[2]  + CC*y[8];
    o[2]  = CC*y[1] + CC*y[2] + CC*y[3]  + CC*y[9];
    o[3]  = CC*y[2] + CC*y[3] + CC*y[4]  + CC*y[10];
    o[4]  = CC*y[3] + CC*y[4] + CC*y[5]  + CC*y[11];
    o[5]  = CC*y[4] + CC*y[5] + CB*y[6]  + CC*y[12];
    o[6]  = CB*y[5] + CA*y[6] + CA*y[13];
    o[7]  = CA*y[0] + CA*y[7] + CB*y[8];
    o[8]  = CC*y[1] + CB*y[7] + CC*y[8]  + CC*y[9];
    o[9]  = CC*y[2] + CC*y[8] + CC*y[9]  + CC*y[10];
    o[10] = CC*y[3] + CC*y[9] + CC*y[10] + CC*y[11];
    o[11] = CC*y[4] + CC*y[10]+ CC*y[11] + CC*y[12];
    o[12] = CC*y[5] + CC*y[11]+ CC*y[12] + CB*y[13];
    o[13] = CA*y[6] + CB*y[12]+ CA*y[13];
}

} // namespace

__global__ void prep_kernel(const float* __restrict__ W1, const float* __restrict__ W2) {
    int t = blockIdx.x * 256 + threadIdx.x;
    if (t < 32768) {
        int n = t >> 8, k = t & 255;
        g_W1h[n * 256 + k] = __float2half_rn(W1[k * 128 + n]);
    } else if (t < 40960) {
        int u = t - 32768;
        int n = u >> 7, k = u & 127;
        g_W2h[n * 128 + k] = __float2half_rn(W2[k * 64 + n]);
    }
}

__global__ void __launch_bounds__(THREADS, 2)
gcn_fp16_kernel(const float* __restrict__ fea,
                const float* __restrict__ b1,
                const float* __restrict__ b2,
                float* __restrict__ out)
{
    extern __shared__ char sm[];
    const uint32_t smb = (uint32_t)__cvta_generic_to_shared(sm);

    float*    b1s = (float*)(sm + O_BIAS);
    float*    b2s = (float*)(sm + O_BIAS + 512);
    float*    Yf  = (float*)(sm + O_Y);
    uint32_t* Xw  = (uint32_t*)(sm + O_X);
    uint32_t* W1w = (uint32_t*)(sm + O_W1);
    float*    Zf  = (float*)(sm + O_Z);
    uint32_t* Hw  = (uint32_t*)(sm + O_H);
    uint32_t* W2w = (uint32_t*)(sm + O_W2);

    const int tid  = threadIdx.x;
    const int warp = tid >> 5;
    const int lane = tid & 31;
    const int g    = lane >> 2;
    const int t    = lane & 3;
    const int wm   = warp >> 1;   // 0..6, M tile of 16 rows
    const int wn   = warp & 1;    // 0..1
    const int blk  = blockIdx.x;

    const float* feaB = fea + (size_t)blk * ROWS * 256;
    const int xrow = tid >> 2;    // 0..111
    const int xseg = tid & 3;     // 0..3 (8-float segment within k32 chunk)

    // ---------------- prologue ----------------
    if (tid < 128) b1s[tid] = b1[tid];
    else if (tid < 192) b2s[tid - 128] = b2[tid - 128];

    // W2T -> smem via cp.async (1024 x 16B)
    for (int i = tid; i < 1024; i += THREADS) {
        int n = i >> 4, seg = i & 15;
        cp16(smb + O_W2 + (uint32_t)(n * W2SW + seg * 4) * 4,
             g_W2h + n * 128 + seg * 8);
    }
    // W1 chunk 0 -> buf 0 (512 x 16B)
    for (int i = tid; i < 512; i += THREADS) {
        int n = i >> 2, seg = i & 3;
        cp16(smb + O_W1 + (uint32_t)(n * WSW + seg * 4) * 4,
             g_W1h + n * 256 + seg * 8);
    }
    cp_commit();

    // X chunk 0 -> buf 0 (f32 LDG -> fp16 cvt -> STS.128), one uint4 per thread
    {
        const float* xp = feaB + xrow * 256 + xseg * 8;
        float4 v0 = *(const float4*)xp;
        float4 v1 = *(const float4*)(xp + 4);
        uint4 u = make_uint4(packh2(v0.x, v0.y), packh2(v0.z, v0.w),
                             packh2(v1.x, v1.y), packh2(v1.z, v1.w));
        *(uint4*)(Xw + xrow * XSW + xseg * 4) = u;
    }
    cp_wait0();
    __syncthreads();

    // ---------------- GEMM1: Y[112,128] = X * W1T^T, K=256 in 8 k32 chunks ----------------
    float acc1[8][4];
    #pragma unroll
    for (int nt = 0; nt < 8; ++nt)
        #pragma unroll
        for (int r = 0; r < 4; ++r) acc1[nt][r] = 0.f;

    #pragma unroll 1
    for (int c = 0; c < 8; ++c) {
        float4 v0, v1;
        if (c < 7) {
            int k0 = (c + 1) * 32;
            const float* xp = feaB + xrow * 256 + k0 + xseg * 8;
            v0 = *(const float4*)xp;
            v1 = *(const float4*)(xp + 4);
            uint32_t wdst = smb + O_W1 + (uint32_t)(((c + 1) & 1) * WBUFW) * 4;
            for (int i = tid; i < 512; i += THREADS) {
                int n = i >> 2, seg = i & 3;
                cp16(wdst + (uint32_t)(n * WSW + seg * 4) * 4,
                     g_W1h + n * 256 + k0 + seg * 8);
            }
            cp_commit();
        }

        const uint32_t* xb = Xw + (c & 1) * XBUFW;
        const uint32_t* wb = W1w + (c & 1) * WBUFW;
        #pragma unroll
        for (int s = 0; s < 2; ++s) {
            const uint32_t* ap = xb + (wm * 16 + g) * XSW + s * 8 + t;
            uint32_t a0 = ap[0];
            uint32_t a1 = ap[8 * XSW];
            uint32_t a2 = ap[4];
            uint32_t a3 = ap[8 * XSW + 4];
            const uint32_t* bp0 = wb + (wn * 64 + g) * WSW + s * 8 + t;
            #pragma unroll
            for (int nt = 0; nt < 8; ++nt) {
                const uint32_t* bp = bp0 + nt * 8 * WSW;
                mma16816(acc1[nt], a0, a1, a2, a3, bp[0], bp[4]);
            }
        }

        if (c < 7) {
            // store X prefetch into the other buffer (last read in iter c-1, synced)
            uint4 u = make_uint4(packh2(v0.x, v0.y), packh2(v0.z, v0.w),
                                 packh2(v1.x, v1.y), packh2(v1.z, v1.w));
            *(uint4*)(Xw + ((c + 1) & 1) * XBUFW + xrow * XSW + xseg * 4) = u;
            cp_wait0();
        }
        __syncthreads();
    }

    // ---------------- Y -> smem (f32) ----------------
    {
        float* yr0 = Yf + (wm * 16 + g) * YSF + wn * 64 + 2 * t;
        float* yr1 = yr0 + 8 * YSF;
        #pragma unroll
        for (int nt = 0; nt < 8; ++nt) {
            *(float2*)(yr0 + nt * 8) = make_float2(acc1[nt][0], acc1[nt][1]);
            *(float2*)(yr1 + nt * 8) = make_float2(acc1[nt][2], acc1[nt][3]);
        }
    }
    __syncthreads();

    // ---------------- A_hat pass 1 (+b1, relu) -> H fp16 ----------------
    const float2* b1s2 = (const float2*)b1s;
    for (int task = tid; task < 512; task += THREADS) {
        int b = task >> 6, wc = task & 63;     // wc = word-col over 128 cols
        const float2* yp = (const float2*)(Yf + b * 14 * YSF) + wc;
        float2 y[14];
        #pragma unroll
        for (int i = 0; i < 14; ++i) y[i] = yp[i * (YSF / 2)];
        float2 bias = b1s2[wc];
        __half2* hp = (__half2*)Hw + b * 14 * HSW + wc;

        float2 o[14];
        o[0]  = m3(CA,y[0], CB,y[1], CA,y[7]);
        o[1]  = m4(CB,y[0], CC,y[1], CC,y[2],  CC,y[8]);
        o[2]  = m4(CC,y[1], CC,y[2], CC,y[3],  CC,y[9]);
        o[3]  = m4(CC,y[2], CC,y[3], CC,y[4],  CC,y[10]);
        o[4]  = m4(CC,y[3], CC,y[4], CC,y[5],  CC,y[11]);
        o[5]  = m4(CC,y[4], CC,y[5], CB,y[6],  CC,y[12]);
        o[6]  = m3(CB,y[5], CA,y[6], CA,y[13]);
        o[7]  = m3(CA,y[0], CA,y[7], CB,y[8]);
        o[8]  = m4(CC,y[1], CB,y[7], CC,y[8],  CC,y[9]);
        o[9]  = m4(CC,y[2], CC,y[8], CC,y[9],  CC,y[10]);
        o[10] = m4(CC,y[3], CC,y[9], CC,y[10], CC,y[11]);
        o[11] = m4(CC,y[4], CC,y[10],CC,y[11], CC,y[12]);
        o[12] = m4(CC,y[5], CC,y[11],CC,y[12], CB,y[13]);
        o[13] = m3(CA,y[6], CB,y[12],CA,y[13]);
        #pragma unroll
        for (int i = 0; i < 14; ++i) {
            float hx = fmaxf(o[i].x + bias.x, 0.f);
            float hy = fmaxf(o[i].y + bias.y, 0.f);
            hp[i * HSW] = __floats2half2_rn(hx, hy);
        }
    }
    __syncthreads();

    // ---------------- GEMM2: Z[112,64] = H * W2T^T, K=128 ----------------
    float acc2[4][4];
    #pragma unroll
    for (int nt = 0; nt < 4; ++nt)
        #pragma unroll
        for (int r = 0; r < 4; ++r) acc2[nt][r] = 0.f;

    #pragma unroll
    for (int s = 0; s < 8; ++s) {
        const uint32_t* ap = Hw + (wm * 16 + g) * HSW + s * 8 + t;
        uint32_t a0 = ap[0];
        uint32_t a1 = ap[8 * HSW];
        uint32_t a2 = ap[4];
        uint32_t a3 = ap[8 * HSW + 4];
        const uint32_t* bp0 = W2w + (wn * 32 + g) * W2SW + s * 8 + t;
        #pragma unroll
        for (int nt = 0; nt < 4; ++nt) {
            const uint32_t* bp = bp0 + nt * 8 * W2SW;
            mma16816(acc2[nt], a0, a1, a2, a3, bp[0], bp[4]);
        }
    }

    // Z -> smem (aliases Y region; H/W2 untouched, Y dead since Ahat1 sync)
    {
        float* zr0 = Zf + (wm * 16 + g) * ZSF + wn * 32 + 2 * t;
        float* zr1 = zr0 + 8 * ZSF;
        #pragma unroll
        for (int nt = 0; nt < 4; ++nt) {
            *(float2*)(zr0 + nt * 8) = make_float2(acc2[nt][0], acc2[nt][1]);
            *(float2*)(zr1 + nt * 8) = make_float2(acc2[nt][2], acc2[nt][3]);
        }
    }
    __syncthreads();

    // ---------------- A_hat pass 2 (+b2) -> global ----------------
    float* gout = out + (size_t)blk * ROWS * 64;
    for (int task = tid; task < 512; task += THREADS) {
        int b = task >> 6, col = task & 63;
        const float* zp = Zf + b * 14 * ZSF + col;
        float z[14], o[14];
        #pragma unroll
        for (int i = 0; i < 14; ++i) z[i] = zp[i * ZSF];
        ahat14(z, o);
        float bv = b2s[col];
        float* gp = gout + (b * 14) * 64 + col;
        #pragma unroll
        for (int i = 0; i < 14; ++i) gp[i * 64] = o[i] + bv;
    }
}

extern "C" void kernel_launch(void* const* d_in, const int* in_sizes, int n_in,
                              void* d_out, int out_size) {
    const float* fea = (const float*)d_in[0];
    const float* W1  = (const float*)d_in[1];
    const float* b1  = (const float*)d_in[2];
    const float* W2  = (const float*)d_in[3];
    const float* b2  = (const float*)d_in[4];
    float* out = (float*)d_out;

    int B = in_sizes[0] / (14 * 256);   // 16384
    int blocks = B / BPB;               // 2048

    prep_kernel<<<160, 256>>>(W1, W2);
    cudaFuncSetAttribute(gcn_fp16_kernel,
                         cudaFuncAttributeMaxDynamicSharedMemorySize, SMEM_BYTES);
    gcn_fp16_kernel<<<blocks, THREADS, SMEM_BYTES>>>(fea, b1, b2, out);
}

// round 8
// speedup vs baseline: 1.5757x; 1.3945x over previous
#include <cuda_runtime.h>
#include <cuda_fp16.h>
#include <cstdint>
#include <cstddef>

// pre-converted fp16 weights, transposed to [n][k]
__device__ __align__(16) __half g_W1h[128 * 256];
__device__ __align__(16) __half g_W2h[64 * 128];

namespace {

constexpr int THREADS = 448;   // 14 warps: 7 M-warps (32 rows) x 2 N-warps (64 cols)
constexpr int BPB     = 16;
constexpr int ROWS    = 224;

constexpr int XSW  = 20;   // X fp16 chunk stride (words): 16 data + 4 pad
constexpr int WSW  = 20;   // W1 fp16 chunk stride
constexpr int HSW  = 68;   // Y/H fp16 stride (words): 64 data + 4 pad
constexpr int W2SW = 68;   // W2T fp16 stride
constexpr int ZSF  = 72;   // Z f32 stride (floats)

constexpr int XBUFW = ROWS * XSW;   // 4480 words per X buffer
constexpr int WBUFW = 128 * WSW;    // 2560 words per W1 buffer

// byte offsets; union region holds {X+W1 staging | YH fp16 | Z f32}
constexpr int O_BIAS = 0;                     // b1(512B)+b2(256B)
constexpr int O_STG  = 1024;
constexpr int O_X    = O_STG;                 // 2*4480*4 = 35840
constexpr int O_W1   = O_STG + 2 * XBUFW * 4; // 36864 (2*2560*4 = 20480)
constexpr int UNION  = 64512;                 // max(56320 staging, 60928 YH, 64512 Z)
constexpr int O_W2   = O_STG + UNION;         // 65536
constexpr int SMEM_BYTES = O_W2 + 64 * W2SW * 4;  // 82944

__device__ __forceinline__ uint32_t packh2(float a, float b) {
    __half2 h = __floats2half2_rn(a, b);
    return *reinterpret_cast<uint32_t*>(&h);
}

__device__ __forceinline__ void mma16816(float* d,
                                         uint32_t a0, uint32_t a1, uint32_t a2, uint32_t a3,
                                         uint32_t b0, uint32_t b1) {
    asm volatile(
        "mma.sync.aligned.m16n8k16.row.col.f32.f16.f16.f32 "
        "{%0,%1,%2,%3},{%4,%5,%6,%7},{%8,%9},{%0,%1,%2,%3};\n"
        : "+f"(d[0]), "+f"(d[1]), "+f"(d[2]), "+f"(d[3])
        : "r"(a0), "r"(a1), "r"(a2), "r"(a3), "r"(b0), "r"(b1));
}

__device__ __forceinline__ void cp16(uint32_t dst_smem, const void* src) {
    asm volatile("cp.async.cg.shared.global [%0], [%1], 16;\n"
                 :: "r"(dst_smem), "l"(src));
}
__device__ __forceinline__ void cp_commit() {
    asm volatile("cp.async.commit_group;\n" ::: "memory");
}
__device__ __forceinline__ void cp_wait0() {
    asm volatile("cp.async.wait_group 0;\n" ::: "memory");
}

// A_hat: degrees (with self-loop) = 3 at teeth {0,6,7,13}, else 4
constexpr float CA = 0.3333333333333333f;
constexpr float CB = 0.28867513459481287f;
constexpr float CC = 0.25f;

__device__ __forceinline__ float2 m3(float wa, float2 a, float wb, float2 b,
                                     float wc, float2 c) {
    return make_float2(wa * a.x + wb * b.x + wc * c.x,
                       wa * a.y + wb * b.y + wc * c.y);
}
__device__ __forceinline__ float2 m4(float wa, float2 a, float wb, float2 b,
                                     float wc, float2 c, float wd, float2 d) {
    return make_float2(wa * a.x + wb * b.x + wc * c.x + wd * d.x,
                       wa * a.y + wb * b.y + wc * c.y + wd * d.y);
}

__device__ __forceinline__ void ahat14(const float* y, float* o) {
    o[0]  = CA*y[0] + CB*y[1] + CA*y[7];
    o[1]  = CB*y[0] + CC*y[1] + CC*y[2]  + CC*y[8];
    o[2]  = CC*y[1] + CC*y[2] + CC*y[3]  + CC*y[9];
    o[3]  = CC*y[2] + CC*y[3] + CC*y[4]  + CC*y[10];
    o[4]  = CC*y[3] + CC*y[4] + CC*y[5]  + CC*y[11];
    o[5]  = CC*y[4] + CC*y[5] + CB*y[6]  + CC*y[12];
    o[6]  = CB*y[5] + CA*y[6] + CA*y[13];
    o[7]  = CA*y[0] + CA*y[7] + CB*y[8];
    o[8]  = CC*y[1] + CB*y[7] + CC*y[8]  + CC*y[9];
    o[9]  = CC*y[2] + CC*y[8] + CC*y[9]  + CC*y[10];
    o[10] = CC*y[3] + CC*y[9] + CC*y[10] + CC*y[11];
    o[11] = CC*y[4] + CC*y[10]+ CC*y[11] + CC*y[12];
    o[12] = CC*y[5] + CC*y[11]+ CC*y[12] + CB*y[13];
    o[13] = CA*y[6] + CB*y[12]+ CA*y[13];
}

} // namespace

__global__ void prep_kernel(const float* __restrict__ W1, const float* __restrict__ W2) {
    int t = blockIdx.x * 256 + threadIdx.x;
    if (t < 32768) {
        int n = t >> 8, k = t & 255;
        g_W1h[n * 256 + k] = __float2half_rn(W1[k * 128 + n]);
    } else if (t < 40960) {
        int u = t - 32768;
        int n = u >> 7, k = u & 127;
        g_W2h[n * 128 + k] = __float2half_rn(W2[k * 64 + n]);
    }
}

__global__ void __launch_bounds__(THREADS, 1)
gcn_mt2_kernel(const float* __restrict__ fea,
               const float* __restrict__ b1,
               const float* __restrict__ b2,
               float* __restrict__ out)
{
    extern __shared__ char sm[];
    const uint32_t smb = (uint32_t)__cvta_generic_to_shared(sm);

    float*    b1s = (float*)(sm + O_BIAS);
    float*    b2s = (float*)(sm + O_BIAS + 512);
    uint32_t* Xw  = (uint32_t*)(sm + O_X);
    uint32_t* W1w = (uint32_t*)(sm + O_W1);
    uint32_t* YHw = (uint32_t*)(sm + O_STG);   // [224][68w] fp16, aliases staging
    float*    Zf  = (float*)(sm + O_STG);      // [224][72]  f32,  aliases staging
    uint32_t* W2w = (uint32_t*)(sm + O_W2);

    const int tid  = threadIdx.x;
    const int warp = tid >> 5;
    const int lane = tid & 31;
    const int g    = lane >> 2;
    const int t    = lane & 3;
    const int wm   = warp >> 1;   // 0..6: 32-row M tile
    const int wn   = warp & 1;    // 0..1: 64-col N tile
    const int blk  = blockIdx.x;

    const float* feaB = fea + (size_t)blk * ROWS * 256;

    // X staging map: 896 uint4 per chunk, 2 per thread
    int xrow[2], xseg[2];
    #pragma unroll
    for (int j = 0; j < 2; ++j) {
        int idx = tid + j * THREADS;
        xrow[j] = idx >> 2;
        xseg[j] = idx & 3;
    }

    // ---------------- prologue ----------------
    if (tid < 128) b1s[tid] = b1[tid];
    else if (tid < 192) b2s[tid - 128] = b2[tid - 128];

    // W2T (64 x 128 halves = 1024 x 16B)
    for (int i = tid; i < 1024; i += THREADS) {
        int n = i >> 4, seg = i & 15;
        cp16(smb + O_W2 + (uint32_t)(n * W2SW + seg * 4) * 4,
             g_W2h + n * 128 + seg * 8);
    }
    // W1 chunk 0 (128 x 32 halves = 512 x 16B)
    for (int i = tid; i < 512; i += THREADS) {
        int n = i >> 2, seg = i & 3;
        cp16(smb + O_W1 + (uint32_t)(n * WSW + seg * 4) * 4,
             g_W1h + n * 256 + seg * 8);
    }
    cp_commit();

    // X chunk 0
    #pragma unroll
    for (int j = 0; j < 2; ++j) {
        const float* xp = feaB + xrow[j] * 256 + xseg[j] * 8;
        float4 v0 = *(const float4*)xp;
        float4 v1 = *(const float4*)(xp + 4);
        *(uint4*)(Xw + xrow[j] * XSW + xseg[j] * 4) =
            make_uint4(packh2(v0.x, v0.y), packh2(v0.z, v0.w),
                       packh2(v1.x, v1.y), packh2(v1.z, v1.w));
    }
    cp_wait0();
    __syncthreads();

    // ---------------- GEMM1: Y[224,128] = X * W1T^T, K=256 ----------------
    float acc1[2][8][4];
    #pragma unroll
    for (int mt = 0; mt < 2; ++mt)
        #pragma unroll
        for (int nt = 0; nt < 8; ++nt)
            #pragma unroll
            for (int r = 0; r < 4; ++r) acc1[mt][nt][r] = 0.f;

    #pragma unroll 1
    for (int c = 0; c < 8; ++c) {
        float4 pv[2][2];
        if (c < 7) {
            int k0 = (c + 1) * 32;
            #pragma unroll
            for (int j = 0; j < 2; ++j) {
                const float* xp = feaB + xrow[j] * 256 + k0 + xseg[j] * 8;
                pv[j][0] = *(const float4*)xp;
                pv[j][1] = *(const float4*)(xp + 4);
            }
            uint32_t wdst = smb + O_W1 + (uint32_t)(((c + 1) & 1) * WBUFW) * 4;
            for (int i = tid; i < 512; i += THREADS) {
                int n = i >> 2, seg = i & 3;
                cp16(wdst + (uint32_t)(n * WSW + seg * 4) * 4,
                     g_W1h + n * 256 + k0 + seg * 8);
            }
            cp_commit();
        }

        const uint32_t* xb = Xw + (c & 1) * XBUFW;
        const uint32_t* wb = W1w + (c & 1) * WBUFW;
        #pragma unroll
        for (int s = 0; s < 2; ++s) {
            uint32_t a[2][4];
            #pragma unroll
            for (int mt = 0; mt < 2; ++mt) {
                const uint32_t* ap = xb + (wm * 32 + mt * 16 + g) * XSW + s * 8 + t;
                a[mt][0] = ap[0];
                a[mt][1] = ap[8 * XSW];
                a[mt][2] = ap[4];
                a[mt][3] = ap[8 * XSW + 4];
            }
            const uint32_t* bp0 = wb + (wn * 64 + g) * WSW + s * 8 + t;
            #pragma unroll
            for (int nt = 0; nt < 8; ++nt) {
                const uint32_t* bp = bp0 + nt * 8 * WSW;
                uint32_t b0 = bp[0], b1v = bp[4];
                mma16816(acc1[0][nt], a[0][0], a[0][1], a[0][2], a[0][3], b0, b1v);
                mma16816(acc1[1][nt], a[1][0], a[1][1], a[1][2], a[1][3], b0, b1v);
            }
        }

        if (c < 7) {
            uint32_t* xw = Xw + ((c + 1) & 1) * XBUFW;
            #pragma unroll
            for (int j = 0; j < 2; ++j) {
                *(uint4*)(xw + xrow[j] * XSW + xseg[j] * 4) =
                    make_uint4(packh2(pv[j][0].x, pv[j][0].y), packh2(pv[j][0].z, pv[j][0].w),
                               packh2(pv[j][1].x, pv[j][1].y), packh2(pv[j][1].z, pv[j][1].w));
            }
            cp_wait0();
        }
        __syncthreads();
    }

    // ---------------- Y -> YH (fp16, aliases staging; GEMM1 done+synced) ----------------
    {
        #pragma unroll
        for (int mt = 0; mt < 2; ++mt) {
            int r0 = wm * 32 + mt * 16 + g;
            __half2* h0 = (__half2*)YHw + r0 * HSW + wn * 32 + t;
            __half2* h1 = h0 + 8 * HSW;
            #pragma unroll
            for (int nt = 0; nt < 8; ++nt) {
                h0[nt * 4] = __floats2half2_rn(acc1[mt][nt][0], acc1[mt][nt][1]);
                h1[nt * 4] = __floats2half2_rn(acc1[mt][nt][2], acc1[mt][nt][3]);
            }
        }
    }
    __syncthreads();

    // ---------------- A_hat pass 1 (+b1, relu), in place on fp16 YH ----------------
    const float2* b1s2 = (const float2*)b1s;
    for (int task = tid; task < BPB * 64; task += THREADS) {
        int b = task >> 6, cw = task & 63;
        __half2* p = (__half2*)YHw + (b * 14) * HSW + cw;
        float2 y[14];
        #pragma unroll
        for (int i = 0; i < 14; ++i) y[i] = __half22float2(p[i * HSW]);
        float2 bias = b1s2[cw];
        float2 o[14];
        o[0]  = m3(CA,y[0], CB,y[1], CA,y[7]);
        o[1]  = m4(CB,y[0], CC,y[1], CC,y[2],  CC,y[8]);
        o[2]  = m4(CC,y[1], CC,y[2], CC,y[3],  CC,y[9]);
        o[3]  = m4(CC,y[2], CC,y[3], CC,y[4],  CC,y[10]);
        o[4]  = m4(CC,y[3], CC,y[4], CC,y[5],  CC,y[11]);
        o[5]  = m4(CC,y[4], CC,y[5], CB,y[6],  CC,y[12]);
        o[6]  = m3(CB,y[5], CA,y[6], CA,y[13]);
        o[7]  = m3(CA,y[0], CA,y[7], CB,y[8]);
        o[8]  = m4(CC,y[1], CB,y[7], CC,y[8],  CC,y[9]);
        o[9]  = m4(CC,y[2], CC,y[8], CC,y[9],  CC,y[10]);
        o[10] = m4(CC,y[3], CC,y[9], CC,y[10], CC,y[11]);
        o[11] = m4(CC,y[4], CC,y[10],CC,y[11], CC,y[12]);
        o[12] = m4(CC,y[5], CC,y[11],CC,y[12], CB,y[13]);
        o[13] = m3(CA,y[6], CB,y[12],CA,y[13]);
        #pragma unroll
        for (int i = 0; i < 14; ++i) {
            p[i * HSW] = __floats2half2_rn(fmaxf(o[i].x + bias.x, 0.f),
                                           fmaxf(o[i].y + bias.y, 0.f));
        }
    }
    __syncthreads();

    // ---------------- GEMM2: Z[224,64] = H * W2T^T, K=128 ----------------
    float acc2[2][4][4];
    #pragma unroll
    for (int mt = 0; mt < 2; ++mt)
        #pragma unroll
        for (int nt = 0; nt < 4; ++nt)
            #pragma unroll
            for (int r = 0; r < 4; ++r) acc2[mt][nt][r] = 0.f;

    #pragma unroll
    for (int s = 0; s < 8; ++s) {
        uint32_t a[2][4];
        #pragma unroll
        for (int mt = 0; mt < 2; ++mt) {
            const uint32_t* ap = YHw + (wm * 32 + mt * 16 + g) * HSW + s * 8 + t;
            a[mt][0] = ap[0];
            a[mt][1] = ap[8 * HSW];
            a[mt][2] = ap[4];
            a[mt][3] = ap[8 * HSW + 4];
        }
        const uint32_t* bp0 = W2w + (wn * 32 + g) * W2SW + s * 8 + t;
        #pragma unroll
        for (int nt = 0; nt < 4; ++nt) {
            const uint32_t* bp = bp0 + nt * 8 * W2SW;
            uint32_t b0 = bp[0], b1v = bp[4];
            mma16816(acc2[0][nt], a[0][0], a[0][1], a[0][2], a[0][3], b0, b1v);
            mma16816(acc2[1][nt], a[1][0], a[1][1], a[1][2], a[1][3], b0, b1v);
        }
    }
    __syncthreads();   // all YH reads done before Z overwrites the region

    // ---------------- Z -> smem (f32) ----------------
    #pragma unroll
    for (int mt = 0; mt < 2; ++mt) {
        int r0 = wm * 32 + mt * 16 + g;
        float* z0 = Zf + r0 * ZSF + wn * 32 + 2 * t;
        float* z1 = z0 + 8 * ZSF;
        #pragma unroll
        for (int nt = 0; nt < 4; ++nt) {
            *(float2*)(z0 + nt * 8) = make_float2(acc2[mt][nt][0], acc2[mt][nt][1]);
            *(float2*)(z1 + nt * 8) = make_float2(acc2[mt][nt][2], acc2[mt][nt][3]);
        }
    }
    __syncthreads();

    // ---------------- A_hat pass 2 (+b2) -> global ----------------
    float* gout = out + (size_t)blk * ROWS * 64;
    for (int task = tid; task < BPB * 64; task += THREADS) {
        int b = task >> 6, col = task & 63;
        const float* zp = Zf + b * 14 * ZSF + col;
        float z[14], o[14];
        #pragma unroll
        for (int i = 0; i < 14; ++i) z[i] = zp[i * ZSF];
        ahat14(z, o);
        float bv = b2s[col];
        float* gp = gout + (b * 14) * 64 + col;
        #pragma unroll
        for (int i = 0; i < 14; ++i) gp[i * 64] = o[i] + bv;
    }
}

extern "C" void kernel_launch(void* const* d_in, const int* in_sizes, int n_in,
                              void* d_out, int out_size) {
    const float* fea = (const float*)d_in[0];
    const float* W1  = (const float*)d_in[1];
    const float* b1  = (const float*)d_in[2];
    const float* W2  = (const float*)d_in[3];
    const float* b2  = (const float*)d_in[4];
    float* out = (float*)d_out;

    int B = in_sizes[0] / (14 * 256);   // 16384
    int blocks = B / BPB;               // 1024

    prep_kernel<<<160, 256>>>(W1, W2);
    cudaFuncSetAttribute(gcn_mt2_kernel,
                         cudaFuncAttributeMaxDynamicSharedMemorySize, SMEM_BYTES);
    gcn_mt2_kernel<<<blocks, THREADS, SMEM_BYTES>>>(fea, b1, b2, out);
}